// round 5
// baseline (speedup 1.0000x reference)
#include <cuda_runtime.h>

// MetaUpscale: x (2,64,128,128) f32, lw (256,256,576,3) f32, scale=2
// out (2,3,256,256) f32
// out[n,ch,oh,ow] = sum_{c9} patch[n, oh/2, ow/2, c9] * lw[oh,ow,c9,ch]
//
// R4: warp = one input pixel, streams its two contiguous 3456-float lw row
// segments as float4 with EXPLICIT group-of-3 prefetch (6 LDG.128 in flight
// per warp minimum). launch_bounds(256,2) -> 128-reg budget so the load
// buffers + 24 accumulators live without spills.

#define HH_   128
#define WW_   128
#define CC_   64
#define C9_   576
#define LWPIX 1728
#define OHW   256
#define PIX_PER_BLK 8

// One float4-pair iteration at compile-time t. SUBV = c9 offset of the active
// subpixel (0 or 576; runtime-select only at t==13). S = subpixel accumulator.
#define DO_ITER(i, t, SUBV, S)                                           \
    do {                                                                 \
        const int g_   = base4 + 128 * (t);                              \
        const int c9g_ = g_ / 3;                                         \
        const int r_   = g_ - 3 * c9g_;                                  \
        const int c9l_ = c9g_ - (SUBV);                                  \
        const float2 pa = pr[c9l_];                                      \
        const float2 pb = pr[c9l_ + 1];                                  \
        const float2 q1 = (r_ >= 2) ? pb : pa;                           \
        const float2 q2 = (r_ >= 1) ? pb : pa;                           \
        const int m0 = (2 * (t)) % 3;                                    \
        const int m1 = (2 * (t) + 1) % 3;                                \
        const int m2 = (2 * (t) + 2) % 3;                                \
        acc[0][S][0][m0] += wa[i].x * pa.x;                              \
        acc[0][S][0][m1] += wa[i].y * q1.x;                              \
        acc[0][S][0][m2] += wa[i].z * q2.x;                              \
        acc[0][S][0][m0] += wa[i].w * pb.x;                              \
        acc[0][S][1][m0] += wa[i].x * pa.y;                              \
        acc[0][S][1][m1] += wa[i].y * q1.y;                              \
        acc[0][S][1][m2] += wa[i].z * q2.y;                              \
        acc[0][S][1][m0] += wa[i].w * pb.y;                              \
        acc[1][S][0][m0] += wb[i].x * pa.x;                              \
        acc[1][S][0][m1] += wb[i].y * q1.x;                              \
        acc[1][S][0][m2] += wb[i].z * q2.x;                              \
        acc[1][S][0][m0] += wb[i].w * pb.x;                              \
        acc[1][S][1][m0] += wb[i].x * pa.y;                              \
        acc[1][S][1][m1] += wb[i].y * q1.y;                              \
        acc[1][S][1][m2] += wb[i].z * q2.y;                              \
        acc[1][S][1][m0] += wb[i].w * pb.y;                              \
    } while (0)

#define LOAD3(T)                                                         \
    wa[0] = __ldcs(&rowA[lane + 32 * (T)]);                              \
    wb[0] = __ldcs(&rowB[lane + 32 * (T)]);                              \
    wa[1] = __ldcs(&rowA[lane + 32 * ((T) + 1)]);                        \
    wb[1] = __ldcs(&rowB[lane + 32 * ((T) + 1)]);                        \
    wa[2] = __ldcs(&rowA[lane + 32 * ((T) + 2)]);                        \
    wb[2] = __ldcs(&rowB[lane + 32 * ((T) + 2)]);

#define GROUP(T, SUBV, S)                                                \
    do {                                                                 \
        LOAD3(T);                                                        \
        DO_ITER(0, (T), SUBV, S);                                        \
        DO_ITER(1, (T) + 1, SUBV, S);                                    \
        DO_ITER(2, (T) + 2, SUBV, S);                                    \
    } while (0)

__global__ __launch_bounds__(256, 2)
void meta_upscale_kernel(const float* __restrict__ x,
                         const float* __restrict__ lw,
                         float* __restrict__ out)
{
    __shared__ float2 prepI[PIX_PER_BLK][C9_];   // {batch0, batch1} per c9

    const int bid = blockIdx.x;          // 2048 = 128 rows x 16 groups of 8 px
    const int hh  = bid >> 4;
    const int gw  = bid & 15;
    const int ww_base = gw * PIX_PER_BLK;
    const int tid = threadIdx.x;

    // ------------- build prepI: 8 pixels x 576 c9, both batches --------------
    for (int idx = tid; idx < PIX_PER_BLK * C9_; idx += 256) {
        const int wp = idx / C9_;
        const int c9 = idx - wp * C9_;
        const int c  = c9 / 9;
        const int r9 = c9 - c * 9;
        const int kh = r9 / 3;
        const int kw = r9 - kh * 3;
        const int y  = hh + kh - 1;
        const int xc = ww_base + wp + kw - 1;
        float v0 = 0.0f, v1 = 0.0f;
        if ((unsigned)y < HH_ && (unsigned)xc < WW_) {
            const int off = (c * HH_ + y) * WW_ + xc;
            v0 = __ldg(x + off);
            v1 = __ldg(x + CC_ * HH_ * WW_ + off);
        }
        prepI[wp][c9] = make_float2(v0, v1);
    }
    __syncthreads();

    // ------------- main loop -------------------------------------------------
    const int w     = tid >> 5;          // warp = pixel index in group
    const int lane  = tid & 31;
    const int ww    = ww_base + w;
    const int oh0   = 2 * hh;
    const int ow0   = 2 * ww;
    const int base4 = 4 * lane;

    const float4* __restrict__ rowA =
        (const float4*)(lw + (size_t)(oh0 * OHW + ow0) * LWPIX);       // 3456 f
    const float4* __restrict__ rowB =
        (const float4*)(lw + (size_t)((oh0 + 1) * OHW + ow0) * LWPIX); // 3456 f
    const float2* __restrict__ pr = &prepI[w][0];

    float acc[2][2][2][3];               // [row][sub][batch][m]
    #pragma unroll
    for (int a = 0; a < 2; a++)
        #pragma unroll
        for (int s = 0; s < 2; s++)
            #pragma unroll
            for (int b = 0; b < 2; b++) {
                acc[a][s][b][0] = 0.f; acc[a][s][b][1] = 0.f; acc[a][s][b][2] = 0.f;
            }

    float4 wa[3], wb[3];

    // t = 0..11 : subpixel 0
    GROUP(0, 0, 0);
    GROUP(3, 0, 0);
    GROUP(6, 0, 0);
    GROUP(9, 0, 0);

    // t = 12,13,14 : boundary group (element 1728 starts at t=13, lane 16)
    {
        LOAD3(12);
        DO_ITER(0, 12, 0, 0);
        {
            const int subv = (lane >= 16) ? 576 : 0;
            if (lane < 16) { DO_ITER(1, 13, subv, 0); }
            else           { DO_ITER(1, 13, subv, 1); }
        }
        DO_ITER(2, 14, 576, 1);
    }

    // t = 15..26 : subpixel 1
    GROUP(15, 576, 1);
    GROUP(18, 576, 1);
    GROUP(21, 576, 1);
    GROUP(24, 576, 1);

    // ------------- remap phase accumulators -> channel order -----------------
    // channel ch lives at m = (ch - p0) mod 3, p0 = lane % 3
    const int p0 = lane % 3;
    float rr[2][2][2][3];
    #pragma unroll
    for (int a = 0; a < 2; a++)
        #pragma unroll
        for (int s = 0; s < 2; s++)
            #pragma unroll
            for (int b = 0; b < 2; b++) {
                rr[a][s][b][0] = (p0 == 0) ? acc[a][s][b][0] : (p0 == 1) ? acc[a][s][b][2] : acc[a][s][b][1];
                rr[a][s][b][1] = (p0 == 0) ? acc[a][s][b][1] : (p0 == 1) ? acc[a][s][b][0] : acc[a][s][b][2];
                rr[a][s][b][2] = (p0 == 0) ? acc[a][s][b][2] : (p0 == 1) ? acc[a][s][b][1] : acc[a][s][b][0];
            }

    // ------------- warp butterfly reduction (24 values) ----------------------
    #pragma unroll
    for (int d = 16; d > 0; d >>= 1) {
        #pragma unroll
        for (int a = 0; a < 2; a++)
            #pragma unroll
            for (int s = 0; s < 2; s++)
                #pragma unroll
                for (int b = 0; b < 2; b++) {
                    rr[a][s][b][0] += __shfl_xor_sync(0xFFFFFFFFu, rr[a][s][b][0], d);
                    rr[a][s][b][1] += __shfl_xor_sync(0xFFFFFFFFu, rr[a][s][b][1], d);
                    rr[a][s][b][2] += __shfl_xor_sync(0xFFFFFFFFu, rr[a][s][b][2], d);
                }
    }

    if (lane == 0) {
        #pragma unroll
        for (int a = 0; a < 2; a++) {
            const int oh = oh0 + a;
            #pragma unroll
            for (int s = 0; s < 2; s++) {
                const int pix = oh * OHW + (ow0 + s);
                #pragma unroll
                for (int b = 0; b < 2; b++) {
                    out[(b * 3 + 0) * OHW * OHW + pix] = rr[a][s][b][0];
                    out[(b * 3 + 1) * OHW * OHW + pix] = rr[a][s][b][1];
                    out[(b * 3 + 2) * OHW * OHW + pix] = rr[a][s][b][2];
                }
            }
        }
    }
}

extern "C" void kernel_launch(void* const* d_in, const int* in_sizes, int n_in,
                              void* d_out, int out_size)
{
    const float* x  = (const float*)d_in[0];   // (2,64,128,128) f32
    const float* lw = (const float*)d_in[1];   // (256,256,576,3) f32
    float* out = (float*)d_out;                // (2,3,256,256) f32

    meta_upscale_kernel<<<128 * 16, 256>>>(x, lw, out);
}

// round 8
// speedup vs baseline: 1.0987x; 1.0987x over previous
#include <cuda_runtime.h>

// MetaUpscale: x (2,64,128,128) f32, lw (256,256,576,3) f32, scale=2
// out (2,3,256,256) f32
// out[n,ch,oh,ow] = sum_{c9} patch[n, oh/2, ow/2, c9] * lw[oh,ow,c9,ch]
//
// R5 (third submission; prior two benches were container-acquisition
// failures): lane owns 12 CONSECUTIVE lw elements per superiteration (3
// float4s), so every lane starts at channel 0: channel mapping is
// uniform/compile-time (no phase rotation, no e/3 division, no remap).
// Patch for those 12 elements is 4 consecutive c9 -> one LDS.128 per batch.
// Warp = one lw row segment (3456 floats, both subpixels); rows A/B warps
// share the pixel's patch. 12 accumulators/warp -> 32 warps/SM.

#define HH_   128
#define WW_   128
#define CC_   64
#define C9_   576
#define LWPIX 1728
#define OHW   256
#define PIX_PER_BLK 8

// Accumulate 12 elements (v0,v1,v2) against patch float4 P into acc[S][b][*].
// Element k (0..11): channel k%3, patch p[k/3] = P.{x,y,z,w}.
#define ACCB(S, b, P)                                                    \
    do {                                                                 \
        acc[S][b][0] += v0.x * P.x;                                      \
        acc[S][b][1] += v0.y * P.x;                                      \
        acc[S][b][2] += v0.z * P.x;                                      \
        acc[S][b][0] += v0.w * P.y;                                      \
        acc[S][b][1] += v1.x * P.y;                                      \
        acc[S][b][2] += v1.y * P.y;                                      \
        acc[S][b][0] += v1.z * P.z;                                      \
        acc[S][b][1] += v1.w * P.z;                                      \
        acc[S][b][2] += v2.x * P.z;                                      \
        acc[S][b][0] += v2.y * P.w;                                      \
        acc[S][b][1] += v2.z * P.w;                                      \
        acc[S][b][2] += v2.w * P.w;                                      \
    } while (0)

// One superiteration at compile-time t (t != 4). POFF: patch f4 offset
// (0 for sub0, 144 for sub1). S: subpixel accumulator slot.
#define SUPER(t, POFF, S)                                                \
    do {                                                                 \
        const float4 v0 = __ldcs(&row[3 * lane + 96 * (t) + 0]);         \
        const float4 v1 = __ldcs(&row[3 * lane + 96 * (t) + 1]);         \
        const float4 v2 = __ldcs(&row[3 * lane + 96 * (t) + 2]);         \
        const float4 P0 = pr0[lane + 32 * (t) - (POFF)];                 \
        const float4 P1 = pr1[lane + 32 * (t) - (POFF)];                 \
        ACCB(S, 0, P0);                                                  \
        ACCB(S, 1, P1);                                                  \
    } while (0)

__global__ __launch_bounds__(512, 2)
void meta_upscale_kernel(const float* __restrict__ x,
                         const float* __restrict__ lw,
                         float* __restrict__ out)
{
    // Patch per pixel, batch-split, float4-viewable: 144 float4 = 576 c9.
    __shared__ float4 prep0[PIX_PER_BLK][C9_ / 4];
    __shared__ float4 prep1[PIX_PER_BLK][C9_ / 4];

    const int bid = blockIdx.x;          // 2048 = 128 rows x 16 groups of 8 px
    const int hh  = bid >> 4;
    const int gw  = bid & 15;
    const int ww_base = gw * PIX_PER_BLK;
    const int tid = threadIdx.x;

    // ------------- build patch: 8 pixels x 576 c9, both batches --------------
    {
        float* p0f = (float*)prep0;
        float* p1f = (float*)prep1;
        for (int idx = tid; idx < PIX_PER_BLK * C9_; idx += 512) {
            const int wp = idx / C9_;
            const int c9 = idx - wp * C9_;
            const int c  = c9 / 9;
            const int r9 = c9 - c * 9;
            const int kh = r9 / 3;
            const int kw = r9 - kh * 3;
            const int y  = hh + kh - 1;
            const int xc = ww_base + wp + kw - 1;
            float v0 = 0.0f, v1 = 0.0f;
            if ((unsigned)y < HH_ && (unsigned)xc < WW_) {
                const int off = (c * HH_ + y) * WW_ + xc;
                v0 = __ldg(x + off);
                v1 = __ldg(x + CC_ * HH_ * WW_ + off);
            }
            p0f[wp * C9_ + c9] = v0;
            p1f[wp * C9_ + c9] = v1;
        }
    }
    __syncthreads();

    // ------------- main loop: warp = one lw row segment ----------------------
    const int w    = tid >> 5;           // 16 warps
    const int lane = tid & 31;
    const int pix  = w >> 1;             // pixel in group
    const int a    = w & 1;              // output row (0: oh0, 1: oh0+1)
    const int ww   = ww_base + pix;
    const int oh0  = 2 * hh;
    const int ow0  = 2 * ww;

    const float4* __restrict__ row =
        (const float4*)(lw + ((size_t)(oh0 + a) * OHW + ow0) * LWPIX); // 3456 f
    const float4* __restrict__ pr0 = &prep0[pix][0];
    const float4* __restrict__ pr1 = &prep1[pix][0];

    float acc[2][2][3];                  // [sub][batch][channel]
    #pragma unroll
    for (int s = 0; s < 2; s++)
        #pragma unroll
        for (int b = 0; b < 2; b++) {
            acc[s][b][0] = 0.f; acc[s][b][1] = 0.f; acc[s][b][2] = 0.f;
        }

    // 9 superiters x 384 elements = 3456. Boundary (elem 1728) at t=4 lane 16.
    SUPER(0, 0, 0);
    SUPER(1, 0, 0);
    SUPER(2, 0, 0);
    SUPER(3, 0, 0);
    {   // t = 4: lanes 0-15 -> sub0 (poff 0), lanes 16-31 -> sub1 (poff 144)
        const float4 v0 = __ldcs(&row[3 * lane + 96 * 4 + 0]);
        const float4 v1 = __ldcs(&row[3 * lane + 96 * 4 + 1]);
        const float4 v2 = __ldcs(&row[3 * lane + 96 * 4 + 2]);
        const int pidx = lane + 32 * 4 - ((lane >= 16) ? 144 : 0);
        const float4 P0 = pr0[pidx];
        const float4 P1 = pr1[pidx];
        if (lane < 16) { ACCB(0, 0, P0); ACCB(0, 1, P1); }
        else           { ACCB(1, 0, P0); ACCB(1, 1, P1); }
    }
    SUPER(5, 144, 1);
    SUPER(6, 144, 1);
    SUPER(7, 144, 1);
    SUPER(8, 144, 1);

    // ------------- warp butterfly reduction (12 values) ----------------------
    #pragma unroll
    for (int d = 16; d > 0; d >>= 1) {
        #pragma unroll
        for (int s = 0; s < 2; s++)
            #pragma unroll
            for (int b = 0; b < 2; b++) {
                acc[s][b][0] += __shfl_xor_sync(0xFFFFFFFFu, acc[s][b][0], d);
                acc[s][b][1] += __shfl_xor_sync(0xFFFFFFFFu, acc[s][b][1], d);
                acc[s][b][2] += __shfl_xor_sync(0xFFFFFFFFu, acc[s][b][2], d);
            }
    }

    if (lane == 0) {
        #pragma unroll
        for (int s = 0; s < 2; s++) {
            const int p = (oh0 + a) * OHW + (ow0 + s);
            #pragma unroll
            for (int b = 0; b < 2; b++) {
                out[(b * 3 + 0) * OHW * OHW + p] = acc[s][b][0];
                out[(b * 3 + 1) * OHW * OHW + p] = acc[s][b][1];
                out[(b * 3 + 2) * OHW * OHW + p] = acc[s][b][2];
            }
        }
    }
}

extern "C" void kernel_launch(void* const* d_in, const int* in_sizes, int n_in,
                              void* d_out, int out_size)
{
    const float* x  = (const float*)d_in[0];   // (2,64,128,128) f32
    const float* lw = (const float*)d_in[1];   // (256,256,576,3) f32
    float* out = (float*)d_out;                // (2,3,256,256) f32

    // 128 rows x 16 groups of 8 pixels; 512 threads = 16 warps
    // (warp = one of 2 lw rows x 8 pixels)
    meta_upscale_kernel<<<128 * 16, 512>>>(x, lw, out);
}

// round 10
// speedup vs baseline: 1.1212x; 1.0205x over previous
#include <cuda_runtime.h>

// MetaUpscale: x (2,64,128,128) f32, lw (256,256,576,3) f32, scale=2
// out (2,3,256,256) f32
// out[n,ch,oh,ow] = sum_{c9} patch[n, oh/2, ow/2, c9] * lw[oh,ow,c9,ch]
//
// R8 = R5 + explicit double-buffered LDG prefetch + pre-sync pipeline prime.
// Lane owns 12 consecutive lw elements per superiter (channel map uniform,
// compile-time); patch = one LDS.128 per batch. Warp = one lw row segment.
// Buffers: A/B of 3 float4 each; loads of superiter t+1 issue before the
// FFMAs of superiter t, so 3-6 LDG.128 stay in flight per warp continuously.

#define HH_   128
#define WW_   128
#define CC_   64
#define C9_   576
#define LWPIX 1728
#define OHW   256
#define PIX_PER_BLK 8

// Accumulate 12 elements (V0,V1,V2) against patch float4 P into acc[S][b][*].
// Element k (0..11): channel k%3, patch p[k/3] = P.{x,y,z,w}.
#define ACCB(S, b, P, V0, V1, V2)                                        \
    do {                                                                 \
        acc[S][b][0] += V0.x * P.x;                                      \
        acc[S][b][1] += V0.y * P.x;                                      \
        acc[S][b][2] += V0.z * P.x;                                      \
        acc[S][b][0] += V0.w * P.y;                                      \
        acc[S][b][1] += V1.x * P.y;                                      \
        acc[S][b][2] += V1.y * P.y;                                      \
        acc[S][b][0] += V1.z * P.z;                                      \
        acc[S][b][1] += V1.w * P.z;                                      \
        acc[S][b][2] += V2.x * P.z;                                      \
        acc[S][b][0] += V2.y * P.w;                                      \
        acc[S][b][1] += V2.z * P.w;                                      \
        acc[S][b][2] += V2.w * P.w;                                      \
    } while (0)

// Issue the 3 LDG.128 of superiter t into buffer B{0,1,2}.
#define LOADG(B0, B1, B2, t)                                             \
    do {                                                                 \
        B0 = __ldcs(&row[3 * lane + 96 * (t) + 0]);                      \
        B1 = __ldcs(&row[3 * lane + 96 * (t) + 1]);                      \
        B2 = __ldcs(&row[3 * lane + 96 * (t) + 2]);                      \
    } while (0)

// Consume buffer for superiter t (t != 4). POFF: 0 (sub0) or 144 (sub1).
#define CONSUME(t, POFF, S, B0, B1, B2)                                  \
    do {                                                                 \
        const float4 P0 = pr0[lane + 32 * (t) - (POFF)];                 \
        const float4 P1 = pr1[lane + 32 * (t) - (POFF)];                 \
        ACCB(S, 0, P0, B0, B1, B2);                                      \
        ACCB(S, 1, P1, B0, B1, B2);                                      \
    } while (0)

__global__ __launch_bounds__(512, 2)
void meta_upscale_kernel(const float* __restrict__ x,
                         const float* __restrict__ lw,
                         float* __restrict__ out)
{
    // Patch per pixel, batch-split, float4-viewable: 144 float4 = 576 c9.
    __shared__ float4 prep0[PIX_PER_BLK][C9_ / 4];
    __shared__ float4 prep1[PIX_PER_BLK][C9_ / 4];

    const int bid = blockIdx.x;          // 2048 = 128 rows x 16 groups of 8 px
    const int hh  = bid >> 4;
    const int gw  = bid & 15;
    const int ww_base = gw * PIX_PER_BLK;
    const int tid = threadIdx.x;

    // ------------- main-loop geometry (needed for the pre-sync prime) --------
    const int w    = tid >> 5;           // 16 warps
    const int lane = tid & 31;
    const int pix  = w >> 1;             // pixel in group
    const int a    = w & 1;              // output row (0: oh0, 1: oh0+1)
    const int ww   = ww_base + pix;
    const int oh0  = 2 * hh;
    const int ow0  = 2 * ww;

    const float4* __restrict__ row =
        (const float4*)(lw + ((size_t)(oh0 + a) * OHW + ow0) * LWPIX); // 3456 f
    const float4* __restrict__ pr0 = &prep0[pix][0];
    const float4* __restrict__ pr1 = &prep1[pix][0];

    // Prime the pipeline: superiter-0 loads touch only gmem, so issue them
    // BEFORE the prep gather — their latency hides under prep + barrier.
    float4 va0, va1, va2, vb0, vb1, vb2;
    LOADG(va0, va1, va2, 0);

    // ------------- build patch: 8 pixels x 576 c9, both batches --------------
    {
        float* p0f = (float*)prep0;
        float* p1f = (float*)prep1;
        for (int idx = tid; idx < PIX_PER_BLK * C9_; idx += 512) {
            const int wp = idx / C9_;
            const int c9 = idx - wp * C9_;
            const int c  = c9 / 9;
            const int r9 = c9 - c * 9;
            const int kh = r9 / 3;
            const int kw = r9 - kh * 3;
            const int y  = hh + kh - 1;
            const int xc = ww_base + wp + kw - 1;
            float v0 = 0.0f, v1 = 0.0f;
            if ((unsigned)y < HH_ && (unsigned)xc < WW_) {
                const int off = (c * HH_ + y) * WW_ + xc;
                v0 = __ldg(x + off);
                v1 = __ldg(x + CC_ * HH_ * WW_ + off);
            }
            p0f[wp * C9_ + c9] = v0;
            p1f[wp * C9_ + c9] = v1;
        }
    }
    __syncthreads();

    float acc[2][2][3];                  // [sub][batch][channel]
    #pragma unroll
    for (int s = 0; s < 2; s++)
        #pragma unroll
        for (int b = 0; b < 2; b++) {
            acc[s][b][0] = 0.f; acc[s][b][1] = 0.f; acc[s][b][2] = 0.f;
        }

    // 9 superiters x 384 elements = 3456. Boundary (elem 1728) at t=4 lane 16.
    // Software pipeline: load t+1 before consuming t.
    LOADG(vb0, vb1, vb2, 1);
    CONSUME(0, 0, 0, va0, va1, va2);

    LOADG(va0, va1, va2, 2);
    CONSUME(1, 0, 0, vb0, vb1, vb2);

    LOADG(vb0, vb1, vb2, 3);
    CONSUME(2, 0, 0, va0, va1, va2);

    LOADG(va0, va1, va2, 4);
    CONSUME(3, 0, 0, vb0, vb1, vb2);

    LOADG(vb0, vb1, vb2, 5);
    {   // t = 4 boundary: lanes 0-15 -> sub0, lanes 16-31 -> sub1 (poff 144)
        const int pidx = lane + 32 * 4 - ((lane >= 16) ? 144 : 0);
        const float4 P0 = pr0[pidx];
        const float4 P1 = pr1[pidx];
        if (lane < 16) {
            ACCB(0, 0, P0, va0, va1, va2);
            ACCB(0, 1, P1, va0, va1, va2);
        } else {
            ACCB(1, 0, P0, va0, va1, va2);
            ACCB(1, 1, P1, va0, va1, va2);
        }
    }

    LOADG(va0, va1, va2, 6);
    CONSUME(5, 144, 1, vb0, vb1, vb2);

    LOADG(vb0, vb1, vb2, 7);
    CONSUME(6, 144, 1, va0, va1, va2);

    LOADG(va0, va1, va2, 8);
    CONSUME(7, 144, 1, vb0, vb1, vb2);

    CONSUME(8, 144, 1, va0, va1, va2);

    // ------------- warp butterfly reduction (12 values) ----------------------
    #pragma unroll
    for (int d = 16; d > 0; d >>= 1) {
        #pragma unroll
        for (int s = 0; s < 2; s++)
            #pragma unroll
            for (int b = 0; b < 2; b++) {
                acc[s][b][0] += __shfl_xor_sync(0xFFFFFFFFu, acc[s][b][0], d);
                acc[s][b][1] += __shfl_xor_sync(0xFFFFFFFFu, acc[s][b][1], d);
                acc[s][b][2] += __shfl_xor_sync(0xFFFFFFFFu, acc[s][b][2], d);
            }
    }

    if (lane == 0) {
        #pragma unroll
        for (int s = 0; s < 2; s++) {
            const int p = (oh0 + a) * OHW + (ow0 + s);
            #pragma unroll
            for (int b = 0; b < 2; b++) {
                out[(b * 3 + 0) * OHW * OHW + p] = acc[s][b][0];
                out[(b * 3 + 1) * OHW * OHW + p] = acc[s][b][1];
                out[(b * 3 + 2) * OHW * OHW + p] = acc[s][b][2];
            }
        }
    }
}

extern "C" void kernel_launch(void* const* d_in, const int* in_sizes, int n_in,
                              void* d_out, int out_size)
{
    const float* x  = (const float*)d_in[0];   // (2,64,128,128) f32
    const float* lw = (const float*)d_in[1];   // (256,256,576,3) f32
    float* out = (float*)d_out;                // (2,3,256,256) f32

    // 128 rows x 16 groups of 8 pixels; 512 threads = 16 warps
    meta_upscale_kernel<<<128 * 16, 512>>>(x, lw, out);
}

// round 11
// speedup vs baseline: 1.1709x; 1.0443x over previous
#include <cuda_runtime.h>

// MetaUpscale: x (2,64,128,128) f32, lw (256,256,576,3) f32, scale=2
// out (2,3,256,256) f32
// out[n,ch,oh,ow] = sum_{c9} patch[n, oh/2, ow/2, c9] * lw[oh,ow,c9,ch]
//
// R10: fix L1 wavefront cost. (a) Main-loop LDG.128 are WARP-CONTIGUOUS
// (row[96t+32k+lane]) -> 4 lines/inst instead of 12 (lane-strided). Channel
// phase (lane-dependent) handled via phase accumulators + epilogue selects;
// patch via interleaved float2{b0,b1} with pa/pb + 2 selects (per-lane
// offsets A_k=(4L+128k)/3 precomputed once). (b) Prep build enumerates
// contiguous x columns (coalesced LDG) and scatters each value to <=3 smem
// slots; pixel stride 577 float2 avoids STS bank conflicts.

#define HH_   128
#define WW_   128
#define CC_   64
#define C9_   576
#define LWPIX 1728
#define OHW   256
#define PIX_PER_BLK 8
#define STR2  577            // float2 stride per pixel in prep (bank-safe)

// Consume one float4 V (4 consecutive lw elements starting at element
// 4*(96t+32k+L)) for subpixel slot S with patch offset OFF (0 or 576).
// pa/pb: the two patch float2{b0,b1} entries; q1/q2 select per r_k.
// Slot m of element j is (2k+j)%3 (compile-time); ch = (L%3 + m) % 3.
#define CONS_K(t, k, S, OFF, V, Ak, N1, N2)                              \
    do {                                                                 \
        const float2 pa = pr[128 * (t) + (Ak) - (OFF)];                  \
        const float2 pb = pr[128 * (t) + (Ak) - (OFF) + 1];              \
        const float2 q1 = (N1) ? pb : pa;                                \
        const float2 q2 = (N2) ? pb : pa;                                \
        const int m0 = (2 * (k)) % 3;                                    \
        const int m1 = (2 * (k) + 1) % 3;                                \
        const int m2 = (2 * (k) + 2) % 3;                                \
        acc[S][0][m0] += V.x * pa.x;  acc[S][1][m0] += V.x * pa.y;       \
        acc[S][0][m1] += V.y * q1.x;  acc[S][1][m1] += V.y * q1.y;       \
        acc[S][0][m2] += V.z * q2.x;  acc[S][1][m2] += V.z * q2.y;       \
        acc[S][0][m0] += V.w * pb.x;  acc[S][1][m0] += V.w * pb.y;       \
    } while (0)

#define CONS(t, S, OFF, B)                                               \
    do {                                                                 \
        CONS_K(t, 0, S, OFF, B[0], A0_, n1_0, n2_0);                     \
        CONS_K(t, 1, S, OFF, B[1], A1_, n1_1, n2_1);                     \
        CONS_K(t, 2, S, OFF, B[2], A2_, n1_2, n2_2);                     \
    } while (0)

#define LOADG(B, t)                                                      \
    do {                                                                 \
        B[0] = __ldcs(&row[96 * (t) + L]);                               \
        B[1] = __ldcs(&row[96 * (t) + 32 + L]);                          \
        B[2] = __ldcs(&row[96 * (t) + 64 + L]);                          \
    } while (0)

__global__ __launch_bounds__(512, 2)
void meta_upscale_kernel(const float* __restrict__ x,
                         const float* __restrict__ lw,
                         float* __restrict__ out)
{
    __shared__ float2 prep[PIX_PER_BLK * STR2];   // {b0,b1} per c9, padded

    const int bid = blockIdx.x;          // 2048 = 128 rows x 16 groups of 8 px
    const int hh  = bid >> 4;
    const int gw  = bid & 15;
    const int ww_base = gw * PIX_PER_BLK;
    const int tid = threadIdx.x;

    const int w    = tid >> 5;           // 16 warps: (pix, output row a)
    const int L    = tid & 31;
    const int pix  = w >> 1;
    const int a    = w & 1;
    const int ww   = ww_base + pix;
    const int oh0  = 2 * hh;
    const int ow0  = 2 * ww;

    const float4* __restrict__ row =
        (const float4*)(lw + ((size_t)(oh0 + a) * OHW + ow0) * LWPIX); // 864 f4
    const float2* __restrict__ pr = &prep[pix * STR2];

    // Per-lane constants for patch addressing / selects (hoisted).
    const int A0_ = (4 * L) / 3;
    const int A1_ = (4 * L + 128) / 3;
    const int A2_ = (4 * L + 256) / 3;
    const int r0_ = L % 3;
    const int r1_ = (L + 2) % 3;
    const int r2_ = (L + 1) % 3;
    const bool n1_0 = (r0_ >= 2), n2_0 = (r0_ >= 1);
    const bool n1_1 = (r1_ >= 2), n2_1 = (r1_ >= 1);
    const bool n1_2 = (r2_ >= 2), n2_2 = (r2_ >= 1);

    // Prime: superiter-0 loads depend only on gmem; hide under prep build.
    float4 va[3], vb[3];
    LOADG(va, 0);

    // ------------- prep build: coalesced x reads, scatter to <=3 slots ------
    // idx enumerates (b, c, kh, u) with u = 10 consecutive x columns
    // (xc = ww_base + u - 1). prep[pix][c*9+kh*3+kw] <- x[b,c,hh+kh-1,xc]
    // where pix = u - kw.
    {
        float* prepf = (float*)prep;
        for (int idx = tid; idx < 2 * CC_ * 3 * 10; idx += 512) {
            const int rowi = idx / 10;
            const int u    = idx - 10 * rowi;
            const int b    = rowi / 192;
            const int rem  = rowi - 192 * b;
            const int c    = rem / 3;
            const int kh   = rem - 3 * c;
            const int y    = hh + kh - 1;
            const int xc   = ww_base + u - 1;
            float xv = 0.0f;
            if ((unsigned)y < HH_ && (unsigned)xc < WW_)
                xv = __ldg(x + ((b * CC_ + c) * HH_ + y) * WW_ + xc);
            const int c9b = c * 9 + kh * 3;
            #pragma unroll
            for (int kw = 0; kw < 3; kw++) {
                const int px = u - kw;
                if ((unsigned)px < PIX_PER_BLK)
                    prepf[(px * STR2 + c9b + kw) * 2 + b] = xv;
            }
        }
    }
    __syncthreads();

    float acc[2][2][3];                  // [sub][batch][slot m]
    #pragma unroll
    for (int s = 0; s < 2; s++)
        #pragma unroll
        for (int b = 0; b < 2; b++) {
            acc[s][b][0] = 0.f; acc[s][b][1] = 0.f; acc[s][b][2] = 0.f;
        }

    // 9 superiters x 384 elements = 3456 (two subpixels; boundary at
    // f4 432 = t=4,k=1,lane 16). Double-buffered: load t+1 before consume t.
    LOADG(vb, 1);
    CONS(0, 0, 0, va);

    LOADG(va, 2);
    CONS(1, 0, 0, vb);

    LOADG(vb, 3);
    CONS(2, 0, 0, va);

    LOADG(va, 4);
    CONS(3, 0, 0, vb);

    LOADG(vb, 5);
    // t = 4: k=0 all sub0; k=1 split at lane 16; k=2 all sub1.
    CONS_K(4, 0, 0, 0, va[0], A0_, n1_0, n2_0);
    if (L < 16) { CONS_K(4, 1, 0, 0,   va[1], A1_, n1_1, n2_1); }
    else        { CONS_K(4, 1, 1, 576, va[1], A1_, n1_1, n2_1); }
    CONS_K(4, 2, 1, 576, va[2], A2_, n1_2, n2_2);

    LOADG(va, 6);
    CONS(5, 1, 576, vb);

    LOADG(vb, 7);
    CONS(6, 1, 576, va);

    LOADG(va, 8);
    CONS(7, 1, 576, vb);

    CONS(8, 1, 576, va);

    // ------------- remap phase slots -> channel order ------------------------
    // channel ch lives at slot (ch - p) mod 3, p = L % 3.
    const int p = r0_;
    float rr[2][2][3];
    #pragma unroll
    for (int s = 0; s < 2; s++)
        #pragma unroll
        for (int b = 0; b < 2; b++) {
            rr[s][b][0] = (p == 0) ? acc[s][b][0] : (p == 1) ? acc[s][b][2] : acc[s][b][1];
            rr[s][b][1] = (p == 0) ? acc[s][b][1] : (p == 1) ? acc[s][b][0] : acc[s][b][2];
            rr[s][b][2] = (p == 0) ? acc[s][b][2] : (p == 1) ? acc[s][b][1] : acc[s][b][0];
        }

    // ------------- warp butterfly reduction (12 values) ----------------------
    #pragma unroll
    for (int d = 16; d > 0; d >>= 1) {
        #pragma unroll
        for (int s = 0; s < 2; s++)
            #pragma unroll
            for (int b = 0; b < 2; b++) {
                rr[s][b][0] += __shfl_xor_sync(0xFFFFFFFFu, rr[s][b][0], d);
                rr[s][b][1] += __shfl_xor_sync(0xFFFFFFFFu, rr[s][b][1], d);
                rr[s][b][2] += __shfl_xor_sync(0xFFFFFFFFu, rr[s][b][2], d);
            }
    }

    if (L == 0) {
        #pragma unroll
        for (int s = 0; s < 2; s++) {
            const int pp = (oh0 + a) * OHW + (ow0 + s);
            #pragma unroll
            for (int b = 0; b < 2; b++) {
                out[(b * 3 + 0) * OHW * OHW + pp] = rr[s][b][0];
                out[(b * 3 + 1) * OHW * OHW + pp] = rr[s][b][1];
                out[(b * 3 + 2) * OHW * OHW + pp] = rr[s][b][2];
            }
        }
    }
}

extern "C" void kernel_launch(void* const* d_in, const int* in_sizes, int n_in,
                              void* d_out, int out_size)
{
    const float* x  = (const float*)d_in[0];   // (2,64,128,128) f32
    const float* lw = (const float*)d_in[1];   // (256,256,576,3) f32
    float* out = (float*)d_out;                // (2,3,256,256) f32

    // 128 rows x 16 groups of 8 pixels; 512 threads = 16 warps
    meta_upscale_kernel<<<128 * 16, 512>>>(x, lw, out);
}

// round 16
// speedup vs baseline: 1.2421x; 1.0608x over previous
#include <cuda_runtime.h>

// MetaUpscale: x (2,64,128,128) f32, lw (256,256,576,3) f32, scale=2
// out (2,3,256,256) f32
// out[n,ch,oh,ow] = sum_{c9} patch[n, oh/2, ow/2, c9] * lw[oh,ow,c9,ch]
//
// R11 = R10 access patterns (warp-contiguous LDG.128, coalesced prep build,
// pre-sync prime) but SINGLE lw buffer and a 42-reg budget so THREE blocks
// fit per SM: 48 warps (75% occ). The extra 16 warps replace the double
// buffer as the latency-hiding mechanism (regfile was the occupancy cap).

#define HH_   128
#define WW_   128
#define CC_   64
#define C9_   576
#define LWPIX 1728
#define OHW   256
#define PIX_PER_BLK 8
#define STR2  577            // float2 stride per pixel in prep (bank-safe)

// Consume one float4 V (4 consecutive lw elements starting at element
// 4*(96t+32k+L)) for subpixel slot S with patch offset OFF (0 or 576).
// Slot m of element j is (2k+j)%3 (compile-time); ch = (L%3 + m) % 3.
#define CONS_K(t, k, S, OFF, V, Ak, N1, N2)                              \
    do {                                                                 \
        const float2 pa = pr[128 * (t) + (Ak) - (OFF)];                  \
        const float2 pb = pr[128 * (t) + (Ak) - (OFF) + 1];              \
        const float2 q1 = (N1) ? pb : pa;                                \
        const float2 q2 = (N2) ? pb : pa;                                \
        const int m0 = (2 * (k)) % 3;                                    \
        const int m1 = (2 * (k) + 1) % 3;                                \
        const int m2 = (2 * (k) + 2) % 3;                                \
        acc[S][0][m0] += V.x * pa.x;  acc[S][1][m0] += V.x * pa.y;       \
        acc[S][0][m1] += V.y * q1.x;  acc[S][1][m1] += V.y * q1.y;       \
        acc[S][0][m2] += V.z * q2.x;  acc[S][1][m2] += V.z * q2.y;       \
        acc[S][0][m0] += V.w * pb.x;  acc[S][1][m0] += V.w * pb.y;       \
    } while (0)

#define CONS(t, S, OFF)                                                  \
    do {                                                                 \
        CONS_K(t, 0, S, OFF, va[0], A0_, n1_0, n2_0);                    \
        CONS_K(t, 1, S, OFF, va[1], A1_, n1_1, n2_1);                    \
        CONS_K(t, 2, S, OFF, va[2], A2_, n1_2, n2_2);                    \
    } while (0)

#define LOADG(t)                                                         \
    do {                                                                 \
        va[0] = __ldcs(&row[96 * (t) + L]);                              \
        va[1] = __ldcs(&row[96 * (t) + 32 + L]);                         \
        va[2] = __ldcs(&row[96 * (t) + 64 + L]);                         \
    } while (0)

__global__ __launch_bounds__(512, 3)
void meta_upscale_kernel(const float* __restrict__ x,
                         const float* __restrict__ lw,
                         float* __restrict__ out)
{
    __shared__ float2 prep[PIX_PER_BLK * STR2];   // {b0,b1} per c9, padded

    const int bid = blockIdx.x;          // 2048 = 128 rows x 16 groups of 8 px
    const int hh  = bid >> 4;
    const int gw  = bid & 15;
    const int ww_base = gw * PIX_PER_BLK;
    const int tid = threadIdx.x;

    const int w    = tid >> 5;           // 16 warps: (pix, output row a)
    const int L    = tid & 31;
    const int pix  = w >> 1;
    const int a    = w & 1;
    const int ww   = ww_base + pix;
    const int oh0  = 2 * hh;
    const int ow0  = 2 * ww;

    const float4* __restrict__ row =
        (const float4*)(lw + ((size_t)(oh0 + a) * OHW + ow0) * LWPIX); // 864 f4
    const float2* __restrict__ pr = &prep[pix * STR2];

    // Per-lane constants for patch addressing / selects (hoisted).
    const int A0_ = (4 * L) / 3;
    const int A1_ = (4 * L + 128) / 3;
    const int A2_ = (4 * L + 256) / 3;
    const int r0_ = L % 3;
    const int r1_ = (L + 2) % 3;
    const int r2_ = (L + 1) % 3;
    const bool n1_0 = (r0_ >= 2), n2_0 = (r0_ >= 1);
    const bool n1_1 = (r1_ >= 2), n2_1 = (r1_ >= 1);
    const bool n1_2 = (r2_ >= 2), n2_2 = (r2_ >= 1);

    // Prime: superiter-0 loads depend only on gmem; hide under prep build.
    float4 va[3];
    LOADG(0);

    // ------------- prep build: coalesced x reads, scatter to <=3 slots ------
    {
        float* prepf = (float*)prep;
        for (int idx = tid; idx < 2 * CC_ * 3 * 10; idx += 512) {
            const int rowi = idx / 10;
            const int u    = idx - 10 * rowi;
            const int b    = rowi / 192;
            const int rem  = rowi - 192 * b;
            const int c    = rem / 3;
            const int kh   = rem - 3 * c;
            const int y    = hh + kh - 1;
            const int xc   = ww_base + u - 1;
            float xv = 0.0f;
            if ((unsigned)y < HH_ && (unsigned)xc < WW_)
                xv = __ldg(x + ((b * CC_ + c) * HH_ + y) * WW_ + xc);
            const int c9b = c * 9 + kh * 3;
            #pragma unroll
            for (int kw = 0; kw < 3; kw++) {
                const int px = u - kw;
                if ((unsigned)px < PIX_PER_BLK)
                    prepf[(px * STR2 + c9b + kw) * 2 + b] = xv;
            }
        }
    }
    __syncthreads();

    float acc[2][2][3];                  // [sub][batch][slot m]
    #pragma unroll
    for (int s = 0; s < 2; s++)
        #pragma unroll
        for (int b = 0; b < 2; b++) {
            acc[s][b][0] = 0.f; acc[s][b][1] = 0.f; acc[s][b][2] = 0.f;
        }

    // 9 superiters x 384 elements = 3456 (two subpixels; boundary at
    // f4 432 = t=4,k=1,lane 16). Single buffer; 48 warps hide latency.
    CONS(0, 0, 0);

    LOADG(1);  CONS(1, 0, 0);
    LOADG(2);  CONS(2, 0, 0);
    LOADG(3);  CONS(3, 0, 0);

    LOADG(4);
    // t = 4: k=0 all sub0; k=1 split at lane 16; k=2 all sub1.
    CONS_K(4, 0, 0, 0, va[0], A0_, n1_0, n2_0);
    if (L < 16) { CONS_K(4, 1, 0, 0,   va[1], A1_, n1_1, n2_1); }
    else        { CONS_K(4, 1, 1, 576, va[1], A1_, n1_1, n2_1); }
    CONS_K(4, 2, 1, 576, va[2], A2_, n1_2, n2_2);

    LOADG(5);  CONS(5, 1, 576);
    LOADG(6);  CONS(6, 1, 576);
    LOADG(7);  CONS(7, 1, 576);
    LOADG(8);  CONS(8, 1, 576);

    // ------------- remap phase slots -> channel order ------------------------
    // channel ch lives at slot (ch - p) mod 3, p = L % 3.
    const int p = r0_;
    float rr[2][2][3];
    #pragma unroll
    for (int s = 0; s < 2; s++)
        #pragma unroll
        for (int b = 0; b < 2; b++) {
            rr[s][b][0] = (p == 0) ? acc[s][b][0] : (p == 1) ? acc[s][b][2] : acc[s][b][1];
            rr[s][b][1] = (p == 0) ? acc[s][b][1] : (p == 1) ? acc[s][b][0] : acc[s][b][2];
            rr[s][b][2] = (p == 0) ? acc[s][b][2] : (p == 1) ? acc[s][b][1] : acc[s][b][0];
        }

    // ------------- warp butterfly reduction (12 values) ----------------------
    #pragma unroll
    for (int d = 16; d > 0; d >>= 1) {
        #pragma unroll
        for (int s = 0; s < 2; s++)
            #pragma unroll
            for (int b = 0; b < 2; b++) {
                rr[s][b][0] += __shfl_xor_sync(0xFFFFFFFFu, rr[s][b][0], d);
                rr[s][b][1] += __shfl_xor_sync(0xFFFFFFFFu, rr[s][b][1], d);
                rr[s][b][2] += __shfl_xor_sync(0xFFFFFFFFu, rr[s][b][2], d);
            }
    }

    if (L == 0) {
        #pragma unroll
        for (int s = 0; s < 2; s++) {
            const int pp = (oh0 + a) * OHW + (ow0 + s);
            #pragma unroll
            for (int b = 0; b < 2; b++) {
                out[(b * 3 + 0) * OHW * OHW + pp] = rr[s][b][0];
                out[(b * 3 + 1) * OHW * OHW + pp] = rr[s][b][1];
                out[(b * 3 + 2) * OHW * OHW + pp] = rr[s][b][2];
            }
        }
    }
}

extern "C" void kernel_launch(void* const* d_in, const int* in_sizes, int n_in,
                              void* d_out, int out_size)
{
    const float* x  = (const float*)d_in[0];   // (2,64,128,128) f32
    const float* lw = (const float*)d_in[1];   // (256,256,576,3) f32
    float* out = (float*)d_out;                // (2,3,256,256) f32

    // 128 rows x 16 groups of 8 pixels; 512 threads = 16 warps, 3 blocks/SM
    meta_upscale_kernel<<<128 * 16, 512>>>(x, lw, out);
}